// round 7
// baseline (speedup 1.0000x reference)
#include <cuda_runtime.h>
#include <cuda_fp16.h>

#define IH 256
#define IW 256
#define NPIX (IH * IW)
#define NMAPS 88
#define SRC_ELEMS (NPIX * 3)

#define QSTRIDE 132
#define QROWS 129
#define COPYSZ (QROWS * QSTRIDE)      // 17028

#define BP 258                        // padded b-plane dim
#define BPL_ELEMS (BP * BP)           // 66564
#define BPL_PAD 66568                 // pad to multiple of 8 halves (16B)
#define SMEM_BYTES (BPL_PAD * 2)      // 133136

#define NUNITS (NMAPS * NPIX / 2)     // 2,883,584 (2 px per unit)
#define PGRID 148
#define PBLOCK 1024
#define STRIDE (PGRID * PBLOCK)       // 151552

// rg-quad: 2x2 corners, each = half2(r,g). [nw,ne,sw,se] = 16B. Parity copies
// (py,px); OOB corners stored zero (bakes the reference masks).
__device__ uint4 g_rgq[4 * COPYSZ];                       // ~1.09 MB
__device__ __align__(16) unsigned short g_bpl[BPL_PAD];   // padded fp16 b-plane

__device__ __forceinline__ unsigned rg_fetch(const float* __restrict__ s, int r, int c) {
    if ((unsigned)r < IH && (unsigned)c < IW) {
        const float* p = s + (r * IW + c) * 3;
        __half2 h = __halves2half2(__float2half(p[0]), __float2half(p[1]));
        return *reinterpret_cast<unsigned*>(&h);
    }
    return 0u;
}

__global__ void pack_src_kernel(const float* __restrict__ src) {
    int t = blockIdx.x * blockDim.x + threadIdx.x;
    if (t < BPL_PAD) {
        int r = t / BP - 1;
        int c = t % BP - 1;
        __half h = (t < BPL_ELEMS && (unsigned)r < IH && (unsigned)c < IW)
                     ? __float2half(src[(r * IW + c) * 3 + 2]) : __float2half(0.f);
        g_bpl[t] = *reinterpret_cast<unsigned short*>(&h);
    }
    if (t < 4 * COPYSZ) {
        int cc  = t / COPYSZ;
        int rem = t % COPYSZ;
        int ky = rem / QSTRIDE;
        int kx = rem % QSTRIDE;
        int py = cc >> 1, px = cc & 1;
        int r0 = 2 * ky - py;
        int c0 = 2 * kx - px;
        uint4 q;
        q.x = rg_fetch(src, r0,     c0);
        q.y = rg_fetch(src, r0,     c0 + 1);
        q.z = rg_fetch(src, r0 + 1, c0);
        q.w = rg_fetch(src, r0 + 1, c0 + 1);
        g_rgq[t] = q;
    }
}

__device__ __forceinline__ float2 u2f(unsigned v) {
    __half2 h = *reinterpret_cast<__half2*>(&v);
    return __half22float2(h);
}

__global__ void __launch_bounds__(PBLOCK, 1) deform_kernel(
    const float* __restrict__ motions, float* __restrict__ out) {
    extern __shared__ char smem[];
    __half* sb = reinterpret_cast<__half*>(smem);

    // fill b-plane: 16B coalesced copies
    {
        const uint4* gq = reinterpret_cast<const uint4*>(g_bpl);
        uint4* sq = reinterpret_cast<uint4*>(smem);
        for (int i = threadIdx.x; i < BPL_PAD / 8; i += PBLOCK)
            sq[i] = gq[i];
    }
    __syncthreads();

    const float4* m4 = reinterpret_cast<const float4*>(motions);
    float2* o2base = reinterpret_cast<float2*>(out);
    int gid = blockIdx.x * PBLOCK + threadIdx.x;

    int u0 = gid, u1 = gid + STRIDE;
    float4 mA = (u0 < NUNITS) ? __ldcs(&m4[u0]) : make_float4(0.f, 0.f, 0.f, 0.f);
    float4 mB = (u1 < NUNITS) ? __ldcs(&m4[u1]) : make_float4(0.f, 0.f, 0.f, 0.f);

    while (u0 < NUNITS) {
        int nu0 = u0 + 2 * STRIDE, nu1 = u1 + 2 * STRIDE;
        float4 cA = mA, cB = mB;
        // prefetch next iteration's motions (hides DRAM latency)
        mA = (nu0 < NUNITS) ? __ldcs(&m4[nu0]) : make_float4(0.f, 0.f, 0.f, 0.f);
        mB = (nu1 < NUNITS) ? __ldcs(&m4[nu1]) : make_float4(0.f, 0.f, 0.f, 0.f);

        float gx[4] = {cA.x, cA.z, cB.x, cB.z};
        float gy[4] = {cA.y, cA.w, cB.y, cB.w};

        float fx[4], fy[4];
        uint4 q[4];
        int bb[4];
#pragma unroll
        for (int s = 0; s < 4; s++) {
            float x = fmaf(gx[s], 128.f, 127.5f);   // [-0.5, 255.5)
            float y = fmaf(gy[s], 128.f, 127.5f);
            int xw = __float2int_rd(x);   // [-1, 255]
            int yn = __float2int_rd(y);   // [-1, 255]
            fx[s] = x - (float)xw;
            fy[s] = y - (float)yn;
            int py = yn & 1, px = xw & 1;
            int ky = (yn + py) >> 1;
            int kx = (xw + px) >> 1;
            q[s] = __ldg(&g_rgq[((py << 1) | px) * COPYSZ + ky * QSTRIDE + kx]);
            bb[s] = (yn + 1) * BP + (xw + 1);
        }

        float bnw[4], bne[4], bsw[4], bse[4];
#pragma unroll
        for (int s = 0; s < 4; s++) {
            bnw[s] = __half2float(sb[bb[s]]);
            bne[s] = __half2float(sb[bb[s] + 1]);
            bsw[s] = __half2float(sb[bb[s] + BP]);
            bse[s] = __half2float(sb[bb[s] + BP + 1]);
        }

        float r[12];
#pragma unroll
        for (int s = 0; s < 4; s++) {
            float wnw = (1.f - fy[s]) * (1.f - fx[s]);
            float wne = (1.f - fy[s]) * fx[s];
            float wsw = fy[s] * (1.f - fx[s]);
            float wse = fy[s] * fx[s];
            float2 nw = u2f(q[s].x), ne = u2f(q[s].y);
            float2 sw = u2f(q[s].z), se = u2f(q[s].w);
            r[s * 3 + 0] = wnw * nw.x + wne * ne.x + wsw * sw.x + wse * se.x;
            r[s * 3 + 1] = wnw * nw.y + wne * ne.y + wsw * sw.y + wse * se.y;
            r[s * 3 + 2] = wnw * bnw[s] + wne * bne[s] + wsw * bsw[s] + wse * bse[s];
        }

        float2* o0 = o2base + (size_t)u0 * 3;
        __stcs(&o0[0], make_float2(r[0], r[1]));
        __stcs(&o0[1], make_float2(r[2], r[3]));
        __stcs(&o0[2], make_float2(r[4], r[5]));
        if (u1 < NUNITS) {
            float2* o1 = o2base + (size_t)u1 * 3;
            __stcs(&o1[0], make_float2(r[6],  r[7]));
            __stcs(&o1[1], make_float2(r[8],  r[9]));
            __stcs(&o1[2], make_float2(r[10], r[11]));
        }
        u0 = nu0;
        u1 = nu1;
    }
}

extern "C" void kernel_launch(void* const* d_in, const int* in_sizes, int n_in,
                              void* d_out, int out_size) {
    const float* source  = (const float*)d_in[0];
    const float* motions = (const float*)d_in[1];
    if (n_in >= 2 && in_sizes[0] != SRC_ELEMS) {
        source  = (const float*)d_in[1];
        motions = (const float*)d_in[0];
    }

    cudaFuncSetAttribute(deform_kernel,
                         cudaFuncAttributeMaxDynamicSharedMemorySize, SMEM_BYTES);

    int pack_threads = 4 * COPYSZ;   // 68112 >= BPL_PAD
    pack_src_kernel<<<(pack_threads + 255) / 256, 256>>>(source);
    deform_kernel<<<PGRID, PBLOCK, SMEM_BYTES>>>(motions, (float*)d_out);
}

// round 8
// speedup vs baseline: 1.2193x; 1.2193x over previous
#include <cuda_runtime.h>
#include <cuda_fp16.h>

#define IH 256
#define IW 256
#define NPIX (IH * IW)
#define NMAPS 88
#define SRC_ELEMS (NPIX * 3)

#define QSTRIDE 132
#define QROWS 129
#define COPYSZ (QROWS * QSTRIDE)    // 17028

// 2x2 fp16 quad, 32B aligned: [0..3]=NW(r,g,b,0) [4..7]=NE [8..11]=SW [12..15]=SE.
// Copy (py,px): quad (ky,kx) covers rows (2ky-py, 2ky-py+1), cols (2kx-px, 2kx-px+1).
// OOB pixels stored zero -> bakes the reference's corner masks.
struct __align__(32) Quad { uint4 a, b; };
__device__ Quad g_quads[4 * COPYSZ];   // ~2.18 MB, L2-resident

__device__ __forceinline__ void px_fetch(const float* __restrict__ s, int r, int c, __half* out) {
    if ((unsigned)r < IH && (unsigned)c < IW) {
        const float* p = s + (r * IW + c) * 3;
        out[0] = __float2half(p[0]);
        out[1] = __float2half(p[1]);
        out[2] = __float2half(p[2]);
        out[3] = __float2half(0.f);
    } else {
        out[0] = out[1] = out[2] = out[3] = __float2half(0.f);
    }
}

__global__ void pack_src_kernel(const float* __restrict__ src) {
    int t = blockIdx.x * blockDim.x + threadIdx.x;
    if (t >= 4 * COPYSZ) return;
    int c   = t / COPYSZ;
    int rem = t % COPYSZ;
    int ky = rem / QSTRIDE;
    int kx = rem % QSTRIDE;
    int py = c >> 1, px = c & 1;
    int r0 = 2 * ky - py;
    int c0 = 2 * kx - px;

    __align__(32) __half h[16];
    px_fetch(src, r0,     c0,     h + 0);
    px_fetch(src, r0,     c0 + 1, h + 4);
    px_fetch(src, r0 + 1, c0,     h + 8);
    px_fetch(src, r0 + 1, c0 + 1, h + 12);
    g_quads[t] = *reinterpret_cast<Quad*>(h);
}

__device__ __forceinline__ float2 h2f(float v) {
    __half2 h = *reinterpret_cast<__half2*>(&v);
    return __half22float2(h);
}

// One thread = 4 consecutive pixels. 88*65536/4 = 1,441,792 threads (5632 x 256).
__global__ void __launch_bounds__(256) deform_kernel(
    const float* __restrict__ motions, float* __restrict__ out) {
    int t = blockIdx.x * blockDim.x + threadIdx.x;

    // motions for 4 pixels: two coalesced 16B streaming loads (evict-first)
    const float4* m4 = reinterpret_cast<const float4*>(motions);
    float4 m0 = __ldcs(&m4[(size_t)t * 2 + 0]);   // x0 y0 x1 y1
    float4 m1 = __ldcs(&m4[(size_t)t * 2 + 1]);   // x2 y2 x3 y3

    float gx[4] = {m0.x, m0.z, m1.x, m1.z};
    float gy[4] = {m0.y, m0.w, m1.y, m1.w};

    float fx[4], fy[4];
    const Quad* qp[4];
#pragma unroll
    for (int s = 0; s < 4; s++) {
        float x = fmaf(gx[s], 128.f, 127.5f);   // [-0.5, 255.5)
        float y = fmaf(gy[s], 128.f, 127.5f);
        int xw = __float2int_rd(x);   // [-1, 255]
        int yn = __float2int_rd(y);   // [-1, 255]
        fx[s] = x - (float)xw;
        fy[s] = y - (float)yn;
        int py = yn & 1, px = xw & 1;
        int ky = (yn + py) >> 1;      // [0,128]
        int kx = (xw + px) >> 1;      // [0,128]
        qp[s] = &g_quads[((py << 1) | px) * COPYSZ + ky * QSTRIDE + kx];
    }

    // 4 independent divergent 256-bit gathers, back-to-back.
    float q[4][8];
#pragma unroll
    for (int s = 0; s < 4; s++) {
        asm("ld.global.nc.v8.f32 {%0,%1,%2,%3,%4,%5,%6,%7}, [%8];"
            : "=f"(q[s][0]), "=f"(q[s][1]), "=f"(q[s][2]), "=f"(q[s][3]),
              "=f"(q[s][4]), "=f"(q[s][5]), "=f"(q[s][6]), "=f"(q[s][7])
            : "l"(qp[s]));
    }

    float r[12];
#pragma unroll
    for (int s = 0; s < 4; s++) {
        float wnw = (1.f - fy[s]) * (1.f - fx[s]);
        float wne = (1.f - fy[s]) * fx[s];
        float wsw = fy[s] * (1.f - fx[s]);
        float wse = fy[s] * fx[s];

        float2 nw = h2f(q[s][0]);
        float2 ne = h2f(q[s][2]);
        float2 sw = h2f(q[s][4]);
        float2 se = h2f(q[s][6]);
        float nwb = h2f(q[s][1]).x;
        float neb = h2f(q[s][3]).x;
        float swb = h2f(q[s][5]).x;
        float seb = h2f(q[s][7]).x;

        r[s * 3 + 0] = wnw * nw.x + wne * ne.x + wsw * sw.x + wse * se.x;
        r[s * 3 + 1] = wnw * nw.y + wne * ne.y + wsw * sw.y + wse * se.y;
        r[s * 3 + 2] = wnw * nwb  + wne * neb  + wsw * swb  + wse * seb;
    }

    // 12 floats per thread: 3 coalesced STG.128 streaming stores.
    float4* o4 = reinterpret_cast<float4*>(out) + (size_t)t * 3;
    __stcs(&o4[0], make_float4(r[0], r[1], r[2],  r[3]));
    __stcs(&o4[1], make_float4(r[4], r[5], r[6],  r[7]));
    __stcs(&o4[2], make_float4(r[8], r[9], r[10], r[11]));
}

extern "C" void kernel_launch(void* const* d_in, const int* in_sizes, int n_in,
                              void* d_out, int out_size) {
    const float* source  = (const float*)d_in[0];
    const float* motions = (const float*)d_in[1];
    if (n_in >= 2 && in_sizes[0] != SRC_ELEMS) {
        source  = (const float*)d_in[1];
        motions = (const float*)d_in[0];
    }

    pack_src_kernel<<<(4 * COPYSZ + 255) / 256, 256>>>(source);

    const int ngroups = NMAPS * NPIX / 4;     // 1,441,792
    deform_kernel<<<ngroups / 256, 256>>>(motions, (float*)d_out);
}